// round 12
// baseline (speedup 1.0000x reference)
#include <cuda_runtime.h>

#define BB 4
#define SS 512
#define HH 128

// 512 blocks x 128 threads. Block owns 4 output rows (t0..t0+3).
// Thread (hq = tid&31, q = tid>>5) owns h-quad {4hq..4hq+3}, k-quarter q (32 k).
// 56 scalar accumulators; software-pipelined mainloop (double-buffered loads).
// q==0 is ONE warp: combines partials, reduces, decides, writes float4 outputs.
__global__ __launch_bounds__(128, 4) void align_kernel(
    const float* __restrict__ x, const float* __restrict__ ref,
    const float* __restrict__ Wa, const float* __restrict__ Wb,
    const float* __restrict__ b1, const float* __restrict__ W2,
    const float* __restrict__ b2, const float* __restrict__ Wp1,
    const float* __restrict__ bp1, const float* __restrict__ Wp2,
    const float* __restrict__ bp2, float* __restrict__ out)
{
    const int tid = threadIdx.x;
    const int q   = tid >> 5;        // k-quarter 0..3
    const int hq  = tid & 31;        // h-quad (h = 4hq .. 4hq+3)
    const int g0  = blockIdx.x * 4;
    const int b   = g0 >> 9;
    const int t0  = g0 & (SS - 1);

    __shared__ float rows2[HH][12];     // [k][x0..x4,pad, r0..r4,pad], 48B stride
    __shared__ float part[3][56][32];   // partials from q = 1..3

    // ---- stage rows transposed: thread tid owns k = tid ----
    {
        const int k = tid;
        #pragma unroll
        for (int r = 0; r < 5; r++) {
            int t  = t0 - 1 + r;
            int tc = t < 0 ? 0 : t;
            const size_t gi = (size_t)(b * SS + tc) * HH + k;
            rows2[k][r]     = x[gi];
            rows2[k][6 + r] = ref[gi];
        }
        rows2[k][5]  = 0.f;
        rows2[k][11] = 0.f;
    }
    __syncthreads();

    // ---- accumulators ----
    float A[5][4], C[5][4], P[4][4];
    {
        const float4 ab = (q == 0) ? ((const float4*)b1)[hq]  : make_float4(0.f, 0.f, 0.f, 0.f);
        const float4 pb = (q == 0) ? ((const float4*)bp1)[hq] : make_float4(0.f, 0.f, 0.f, 0.f);
        #pragma unroll
        for (int r = 0; r < 5; r++) {
            A[r][0] = ab.x; A[r][1] = ab.y; A[r][2] = ab.z; A[r][3] = ab.w;
            C[r][0] = 0.f;  C[r][1] = 0.f;  C[r][2] = 0.f;  C[r][3] = 0.f;
        }
        #pragma unroll
        for (int r = 0; r < 4; r++) {
            P[r][0] = pb.x; P[r][1] = pb.y; P[r][2] = pb.z; P[r][3] = pb.w;
        }
    }

    const float4* __restrict__ Wa4 = (const float4*)Wa;   // [k*32 + hq]
    const float4* __restrict__ Wb4 = (const float4*)Wb;
    const float4* __restrict__ Wp4 = (const float4*)Wp1;

    const int kb = q * 32;

    // ---- software-pipelined mainloop: prefetch iter kk+1 before FMAs of kk ----
    float4 wa_c = Wa4[kb * 32 + hq];
    float4 wb_c = Wb4[kb * 32 + hq];
    float4 wp_c = Wp4[kb * 32 + hq];
    float4 u0_c = *(const float4*)&rows2[kb][0];
    float4 u1_c = *(const float4*)&rows2[kb][4];
    float4 u2_c = *(const float4*)&rows2[kb][8];

    #pragma unroll 2
    for (int kk = 0; kk < 32; kk++) {
        // branchless prefetch of next iteration (clamped re-load on last iter)
        const int kn = kb + ((kk < 31) ? (kk + 1) : 31);
        float4 wa_n = Wa4[kn * 32 + hq];
        float4 wb_n = Wb4[kn * 32 + hq];
        float4 wp_n = Wp4[kn * 32 + hq];
        float4 u0_n = *(const float4*)&rows2[kn][0];
        float4 u1_n = *(const float4*)&rows2[kn][4];
        float4 u2_n = *(const float4*)&rows2[kn][8];

        const float xv[5]  = {u0_c.x, u0_c.y, u0_c.z, u0_c.w, u1_c.x};
        const float rv[5]  = {u1_c.z, u1_c.w, u2_c.x, u2_c.y, u2_c.z};
        const float waj[4] = {wa_c.x, wa_c.y, wa_c.z, wa_c.w};
        const float wbj[4] = {wb_c.x, wb_c.y, wb_c.z, wb_c.w};
        const float wpj[4] = {wp_c.x, wp_c.y, wp_c.z, wp_c.w};
        #pragma unroll
        for (int r = 0; r < 5; r++) {
            #pragma unroll
            for (int j = 0; j < 4; j++) {
                A[r][j] = fmaf(xv[r], waj[j], A[r][j]);
                C[r][j] = fmaf(rv[r], wbj[j], C[r][j]);
            }
        }
        #pragma unroll
        for (int r = 0; r < 4; r++) {
            #pragma unroll
            for (int j = 0; j < 4; j++)
                P[r][j] = fmaf(xv[r + 1], wpj[j], P[r][j]);
        }

        wa_c = wa_n; wb_c = wb_n; wp_c = wp_n;
        u0_c = u0_n; u1_c = u1_n; u2_c = u2_n;
    }

    // ---- publish partials (q = 1..3) ----
    if (q != 0) {
        #pragma unroll
        for (int r = 0; r < 5; r++) {
            #pragma unroll
            for (int j = 0; j < 4; j++) {
                part[q - 1][r * 4 + j][hq]      = A[r][j];
                part[q - 1][20 + r * 4 + j][hq] = C[r][j];
            }
        }
        #pragma unroll
        for (int r = 0; r < 4; r++) {
            #pragma unroll
            for (int j = 0; j < 4; j++)
                part[q - 1][40 + r * 4 + j][hq] = P[r][j];
        }
    }
    __syncthreads();

    // ---- q == 0: one warp finishes the block ----
    if (q == 0) {
        #pragma unroll
        for (int r = 0; r < 5; r++) {
            #pragma unroll
            for (int j = 0; j < 4; j++) {
                const int d = r * 4 + j;
                A[r][j] += part[0][d][hq]      + part[1][d][hq]      + part[2][d][hq];
                C[r][j] += part[0][20 + d][hq] + part[1][20 + d][hq] + part[2][20 + d][hq];
            }
        }
        #pragma unroll
        for (int r = 0; r < 4; r++) {
            #pragma unroll
            for (int j = 0; j < 4; j++) {
                const int d = 40 + r * 4 + j;
                P[r][j] += part[0][d][hq] + part[1][d][hq] + part[2][d][hq];
                P[r][j]  = fmaxf(P[r][j], 0.f);
            }
        }

        const float4 w2v = ((const float4*)W2)[hq];
        const float  w2a[4] = {w2v.x, w2v.y, w2v.z, w2v.w};
        const float4* wpq = (const float4*)&Wp2[12 * hq];
        const float4 q0v = wpq[0], q1v = wpq[1], q2v = wpq[2];
        const float wq[12] = {q0v.x, q0v.y, q0v.z, q0v.w,
                              q1v.x, q1v.y, q1v.z, q1v.w,
                              q2v.x, q2v.y, q2v.z, q2v.w};
        const float b2s  = b2[0];
        const float bp20 = bp2[0], bp21 = bp2[1], bp22 = bp2[2];

        #pragma unroll
        for (int i = 0; i < 4; i++) {
            const int t = t0 + i;
            float v[6] = {0.f, 0.f, 0.f, 0.f, 0.f, 0.f};
            #pragma unroll
            for (int j = 0; j < 4; j++) {
                v[0] += fmaxf(A[i + 1][j] + C[i + 1][j], 0.f) * w2a[j];  // A[t,t]
                v[1] += fmaxf(A[i][j]     + C[i + 1][j], 0.f) * w2a[j];  // A[t-1,t]
                v[2] += fmaxf(A[i + 1][j] + C[i][j],     0.f) * w2a[j];  // A[t,t-1]
                const float pj = P[i][j];
                v[3] += pj * wq[3 * j + 0];
                v[4] += pj * wq[3 * j + 1];
                v[5] += pj * wq[3 * j + 2];
            }
            #pragma unroll
            for (int j = 0; j < 6; j++) {
                float s = v[j];
                s += __shfl_xor_sync(0xffffffffu, s, 16);
                s += __shfl_xor_sync(0xffffffffu, s, 8);
                s += __shfl_xor_sync(0xffffffffu, s, 4);
                s += __shfl_xor_sync(0xffffffffu, s, 2);
                s += __shfl_xor_sync(0xffffffffu, s, 1);
                v[j] = s;   // all lanes hold the full sum
            }

            // decision, computed redundantly on all 32 lanes
            int   op    = -1;    // -1 => copy x (t == 0)
            float alpha = 0.f;
            const float Ad = 1.0f / (1.0f + expf(-(v[0] + b2s)));
            if (t != 0) {
                const float Ai   = 1.0f / (1.0f + expf(-(v[1] + b2s)));
                const float Adel = 1.0f / (1.0f + expf(-(v[2] + b2s)));
                const float l0 = v[3] + bp20;
                const float l1 = v[4] + bp21;
                const float l2 = v[5] + bp22;
                const float mx  = fmaxf(l0, fmaxf(l1, l2));
                const float lse = mx + logf(expf(l0 - mx) + expf(l1 - mx) + expf(l2 - mx));
                const float m   = Ad   * (l0 - lse);
                const float ins = Ai   * (l1 - lse);
                const float del = Adel * (l2 - lse);
                if (m >= ins && m >= del) op = 0;   // first-max tie-break == jnp.argmax
                else if (ins >= del)      op = 1;
                else                      op = 2;
                alpha = Ad;
            }

            float o[4];
            #pragma unroll
            for (int j = 0; j < 4; j++) {
                const int hcol = 4 * hq + j;
                const float cx = rows2[hcol][i + 1];  // x[t]
                const float cr = rows2[hcol][7 + i];  // ref[t]
                const float px = rows2[hcol][i];      // x[t-1]
                if (op < 0)       o[j] = cx;
                else if (op == 0) o[j] = (1.f - alpha) * cx + alpha * cr;
                else if (op == 1) o[j] = cr;
                else              o[j] = px;
            }
            *(float4*)&out[(size_t)(b * SS + t) * HH + 4 * hq] =
                make_float4(o[0], o[1], o[2], o[3]);
        }
    }
}

extern "C" void kernel_launch(void* const* d_in, const int* in_sizes, int n_in,
                              void* d_out, int out_size) {
    const float* x   = (const float*)d_in[0];
    const float* ref = (const float*)d_in[1];
    const float* Wa  = (const float*)d_in[2];
    const float* Wb  = (const float*)d_in[3];
    const float* b1  = (const float*)d_in[4];
    const float* W2  = (const float*)d_in[5];
    const float* b2  = (const float*)d_in[6];
    const float* Wp1 = (const float*)d_in[7];
    const float* bp1 = (const float*)d_in[8];
    const float* Wp2 = (const float*)d_in[9];
    const float* bp2 = (const float*)d_in[10];

    dim3 grid(BB * SS / 4);   // 512 blocks
    dim3 block(128);          // 32 h-quads x 4 k-quarters
    align_kernel<<<grid, block>>>(x, ref, Wa, Wb, b1, W2, b2,
                                  Wp1, bp1, Wp2, bp2, (float*)d_out);
}

// round 13
// speedup vs baseline: 1.3212x; 1.3212x over previous
#include <cuda_runtime.h>

#define BB 4
#define SS 512
#define HH 128

// 512 blocks x 128 threads. Block owns 4 output rows (t0..t0+3).
// Thread (hq = tid&31, q = tid>>5) owns h-quad {4hq..4hq+3}, k-quarter q (32 k).
// 56 scalar accumulators. GMEM weight loads software-pipelined one iteration
// ahead (prologue / steady / epilogue); smem row broadcasts stay in-loop.
// q==0 is ONE warp: combines partials, reduces, decides, writes float4 outputs.
__global__ __launch_bounds__(128, 4) void align_kernel(
    const float* __restrict__ x, const float* __restrict__ ref,
    const float* __restrict__ Wa, const float* __restrict__ Wb,
    const float* __restrict__ b1, const float* __restrict__ W2,
    const float* __restrict__ b2, const float* __restrict__ Wp1,
    const float* __restrict__ bp1, const float* __restrict__ Wp2,
    const float* __restrict__ bp2, float* __restrict__ out)
{
    const int tid = threadIdx.x;
    const int q   = tid >> 5;        // k-quarter 0..3
    const int hq  = tid & 31;        // h-quad (h = 4hq .. 4hq+3)
    const int g0  = blockIdx.x * 4;
    const int b   = g0 >> 9;
    const int t0  = g0 & (SS - 1);

    __shared__ float rows2[HH][12];     // [k][x0..x4,pad, r0..r4,pad], 48B stride
    __shared__ float part[3][56][32];   // partials from q = 1..3

    // ---- stage rows transposed: thread tid owns k = tid ----
    {
        const int k = tid;
        #pragma unroll
        for (int r = 0; r < 5; r++) {
            int t  = t0 - 1 + r;
            int tc = t < 0 ? 0 : t;
            const size_t gi = (size_t)(b * SS + tc) * HH + k;
            rows2[k][r]     = x[gi];
            rows2[k][6 + r] = ref[gi];
        }
        rows2[k][5]  = 0.f;
        rows2[k][11] = 0.f;
    }
    __syncthreads();

    // ---- accumulators ----
    float A[5][4], C[5][4], P[4][4];
    {
        const float4 ab = (q == 0) ? ((const float4*)b1)[hq]  : make_float4(0.f, 0.f, 0.f, 0.f);
        const float4 pb = (q == 0) ? ((const float4*)bp1)[hq] : make_float4(0.f, 0.f, 0.f, 0.f);
        #pragma unroll
        for (int r = 0; r < 5; r++) {
            A[r][0] = ab.x; A[r][1] = ab.y; A[r][2] = ab.z; A[r][3] = ab.w;
            C[r][0] = 0.f;  C[r][1] = 0.f;  C[r][2] = 0.f;  C[r][3] = 0.f;
        }
        #pragma unroll
        for (int r = 0; r < 4; r++) {
            P[r][0] = pb.x; P[r][1] = pb.y; P[r][2] = pb.z; P[r][3] = pb.w;
        }
    }

    const float4* __restrict__ Wa4 = (const float4*)Wa;   // [k*32 + hq]
    const float4* __restrict__ Wb4 = (const float4*)Wb;
    const float4* __restrict__ Wp4 = (const float4*)Wp1;

    const int kb = q * 32;

    // ---- prologue: load weights for first iteration ----
    float4 wa_c = Wa4[kb * 32 + hq];
    float4 wb_c = Wb4[kb * 32 + hq];
    float4 wp_c = Wp4[kb * 32 + hq];

    #pragma unroll 2
    for (int kk = 0; kk < 31; kk++) {
        const int k  = kb + kk;
        // prefetch next iteration's weights (GMEM) before this iter's FMAs
        float4 wa_n = Wa4[(k + 1) * 32 + hq];
        float4 wb_n = Wb4[(k + 1) * 32 + hq];
        float4 wp_n = Wp4[(k + 1) * 32 + hq];

        const float4 u0 = *(const float4*)&rows2[k][0];   // x0 x1 x2 x3
        const float4 u1 = *(const float4*)&rows2[k][4];   // x4 pad r0 r1
        const float4 u2 = *(const float4*)&rows2[k][8];   // r2 r3 r4 pad
        const float xv[5]  = {u0.x, u0.y, u0.z, u0.w, u1.x};
        const float rv[5]  = {u1.z, u1.w, u2.x, u2.y, u2.z};
        const float waj[4] = {wa_c.x, wa_c.y, wa_c.z, wa_c.w};
        const float wbj[4] = {wb_c.x, wb_c.y, wb_c.z, wb_c.w};
        const float wpj[4] = {wp_c.x, wp_c.y, wp_c.z, wp_c.w};
        #pragma unroll
        for (int r = 0; r < 5; r++) {
            #pragma unroll
            for (int j = 0; j < 4; j++) {
                A[r][j] = fmaf(xv[r], waj[j], A[r][j]);
                C[r][j] = fmaf(rv[r], wbj[j], C[r][j]);
            }
        }
        #pragma unroll
        for (int r = 0; r < 4; r++) {
            #pragma unroll
            for (int j = 0; j < 4; j++)
                P[r][j] = fmaf(xv[r + 1], wpj[j], P[r][j]);
        }

        wa_c = wa_n; wb_c = wb_n; wp_c = wp_n;
    }
    // ---- epilogue: final iteration (kk = 31), no prefetch ----
    {
        const int k = kb + 31;
        const float4 u0 = *(const float4*)&rows2[k][0];
        const float4 u1 = *(const float4*)&rows2[k][4];
        const float4 u2 = *(const float4*)&rows2[k][8];
        const float xv[5]  = {u0.x, u0.y, u0.z, u0.w, u1.x};
        const float rv[5]  = {u1.z, u1.w, u2.x, u2.y, u2.z};
        const float waj[4] = {wa_c.x, wa_c.y, wa_c.z, wa_c.w};
        const float wbj[4] = {wb_c.x, wb_c.y, wb_c.z, wb_c.w};
        const float wpj[4] = {wp_c.x, wp_c.y, wp_c.z, wp_c.w};
        #pragma unroll
        for (int r = 0; r < 5; r++) {
            #pragma unroll
            for (int j = 0; j < 4; j++) {
                A[r][j] = fmaf(xv[r], waj[j], A[r][j]);
                C[r][j] = fmaf(rv[r], wbj[j], C[r][j]);
            }
        }
        #pragma unroll
        for (int r = 0; r < 4; r++) {
            #pragma unroll
            for (int j = 0; j < 4; j++)
                P[r][j] = fmaf(xv[r + 1], wpj[j], P[r][j]);
        }
    }

    // ---- publish partials (q = 1..3) ----
    if (q != 0) {
        #pragma unroll
        for (int r = 0; r < 5; r++) {
            #pragma unroll
            for (int j = 0; j < 4; j++) {
                part[q - 1][r * 4 + j][hq]      = A[r][j];
                part[q - 1][20 + r * 4 + j][hq] = C[r][j];
            }
        }
        #pragma unroll
        for (int r = 0; r < 4; r++) {
            #pragma unroll
            for (int j = 0; j < 4; j++)
                part[q - 1][40 + r * 4 + j][hq] = P[r][j];
        }
    }
    __syncthreads();

    // ---- q == 0: one warp finishes the block ----
    if (q == 0) {
        #pragma unroll
        for (int r = 0; r < 5; r++) {
            #pragma unroll
            for (int j = 0; j < 4; j++) {
                const int d = r * 4 + j;
                A[r][j] += part[0][d][hq]      + part[1][d][hq]      + part[2][d][hq];
                C[r][j] += part[0][20 + d][hq] + part[1][20 + d][hq] + part[2][20 + d][hq];
            }
        }
        #pragma unroll
        for (int r = 0; r < 4; r++) {
            #pragma unroll
            for (int j = 0; j < 4; j++) {
                const int d = 40 + r * 4 + j;
                P[r][j] += part[0][d][hq] + part[1][d][hq] + part[2][d][hq];
                P[r][j]  = fmaxf(P[r][j], 0.f);
            }
        }

        const float4 w2v = ((const float4*)W2)[hq];
        const float  w2a[4] = {w2v.x, w2v.y, w2v.z, w2v.w};
        const float4* wpq = (const float4*)&Wp2[12 * hq];
        const float4 q0v = wpq[0], q1v = wpq[1], q2v = wpq[2];
        const float wq[12] = {q0v.x, q0v.y, q0v.z, q0v.w,
                              q1v.x, q1v.y, q1v.z, q1v.w,
                              q2v.x, q2v.y, q2v.z, q2v.w};
        const float b2s  = b2[0];
        const float bp20 = bp2[0], bp21 = bp2[1], bp22 = bp2[2];

        #pragma unroll
        for (int i = 0; i < 4; i++) {
            const int t = t0 + i;
            float v[6] = {0.f, 0.f, 0.f, 0.f, 0.f, 0.f};
            #pragma unroll
            for (int j = 0; j < 4; j++) {
                v[0] += fmaxf(A[i + 1][j] + C[i + 1][j], 0.f) * w2a[j];  // A[t,t]
                v[1] += fmaxf(A[i][j]     + C[i + 1][j], 0.f) * w2a[j];  // A[t-1,t]
                v[2] += fmaxf(A[i + 1][j] + C[i][j],     0.f) * w2a[j];  // A[t,t-1]
                const float pj = P[i][j];
                v[3] += pj * wq[3 * j + 0];
                v[4] += pj * wq[3 * j + 1];
                v[5] += pj * wq[3 * j + 2];
            }
            #pragma unroll
            for (int j = 0; j < 6; j++) {
                float s = v[j];
                s += __shfl_xor_sync(0xffffffffu, s, 16);
                s += __shfl_xor_sync(0xffffffffu, s, 8);
                s += __shfl_xor_sync(0xffffffffu, s, 4);
                s += __shfl_xor_sync(0xffffffffu, s, 2);
                s += __shfl_xor_sync(0xffffffffu, s, 1);
                v[j] = s;   // all lanes hold the full sum
            }

            // decision, computed redundantly on all 32 lanes
            int   op    = -1;    // -1 => copy x (t == 0)
            float alpha = 0.f;
            const float Ad = 1.0f / (1.0f + expf(-(v[0] + b2s)));
            if (t != 0) {
                const float Ai   = 1.0f / (1.0f + expf(-(v[1] + b2s)));
                const float Adel = 1.0f / (1.0f + expf(-(v[2] + b2s)));
                const float l0 = v[3] + bp20;
                const float l1 = v[4] + bp21;
                const float l2 = v[5] + bp22;
                const float mx  = fmaxf(l0, fmaxf(l1, l2));
                const float lse = mx + logf(expf(l0 - mx) + expf(l1 - mx) + expf(l2 - mx));
                const float m   = Ad   * (l0 - lse);
                const float ins = Ai   * (l1 - lse);
                const float del = Adel * (l2 - lse);
                if (m >= ins && m >= del) op = 0;   // first-max tie-break == jnp.argmax
                else if (ins >= del)      op = 1;
                else                      op = 2;
                alpha = Ad;
            }

            float o[4];
            #pragma unroll
            for (int j = 0; j < 4; j++) {
                const int hcol = 4 * hq + j;
                const float cx = rows2[hcol][i + 1];  // x[t]
                const float cr = rows2[hcol][7 + i];  // ref[t]
                const float px = rows2[hcol][i];      // x[t-1]
                if (op < 0)       o[j] = cx;
                else if (op == 0) o[j] = (1.f - alpha) * cx + alpha * cr;
                else if (op == 1) o[j] = cr;
                else              o[j] = px;
            }
            *(float4*)&out[(size_t)(b * SS + t) * HH + 4 * hq] =
                make_float4(o[0], o[1], o[2], o[3]);
        }
    }
}

extern "C" void kernel_launch(void* const* d_in, const int* in_sizes, int n_in,
                              void* d_out, int out_size) {
    const float* x   = (const float*)d_in[0];
    const float* ref = (const float*)d_in[1];
    const float* Wa  = (const float*)d_in[2];
    const float* Wb  = (const float*)d_in[3];
    const float* b1  = (const float*)d_in[4];
    const float* W2  = (const float*)d_in[5];
    const float* b2  = (const float*)d_in[6];
    const float* Wp1 = (const float*)d_in[7];
    const float* bp1 = (const float*)d_in[8];
    const float* Wp2 = (const float*)d_in[9];
    const float* bp2 = (const float*)d_in[10];

    dim3 grid(BB * SS / 4);   // 512 blocks
    dim3 block(128);          // 32 h-quads x 4 k-quarters
    align_kernel<<<grid, block>>>(x, ref, Wa, Wb, b1, W2, b2,
                                  Wp1, bp1, Wp2, bp2, (float*)d_out);
}

// round 14
// speedup vs baseline: 1.5424x; 1.1674x over previous
#include <cuda_runtime.h>

#define BB 4
#define SS 512
#define HH 128

// 592 blocks (148 per batch => exactly 4 blocks/SM, one balanced wave) x 128 threads.
// Per batch: blocks 0..67 own 4 rows, blocks 68..147 own 3 rows (run the same
// 4-row code with clamped reads; 4th store guarded off).
// Thread (hq = tid&31, q = tid>>5) owns h-quad {4hq..4hq+3}, k-quarter q (32 k).
// 56 scalar accumulators; GMEM weight loads software-pipelined one iter ahead.
// q==0 is ONE warp: combines partials, reduces, decides, writes float4 outputs.
__global__ __launch_bounds__(128, 4) void align_kernel(
    const float* __restrict__ x, const float* __restrict__ ref,
    const float* __restrict__ Wa, const float* __restrict__ Wb,
    const float* __restrict__ b1, const float* __restrict__ W2,
    const float* __restrict__ b2, const float* __restrict__ Wp1,
    const float* __restrict__ bp1, const float* __restrict__ Wp2,
    const float* __restrict__ bp2, float* __restrict__ out)
{
    const int tid = threadIdx.x;
    const int q   = tid >> 5;        // k-quarter 0..3
    const int hq  = tid & 31;        // h-quad (h = 4hq .. 4hq+3)

    const int b   = blockIdx.x / 148;         // batch
    const int ib  = blockIdx.x - b * 148;     // block-in-batch 0..147
    int t0, cnt;
    if (ib < 68) { t0 = ib * 4;               cnt = 4; }
    else         { t0 = 272 + (ib - 68) * 3;  cnt = 3; }

    __shared__ float rows2[HH][12];     // [k][x0..x4,pad, r0..r4,pad], 48B stride
    __shared__ float part[3][56][32];   // partials from q = 1..3

    // ---- stage rows transposed: thread tid owns k = tid ----
    {
        const int k = tid;
        #pragma unroll
        for (int r = 0; r < 5; r++) {
            int t  = t0 - 1 + r;
            int tc = t < 0 ? 0 : (t > SS - 1 ? SS - 1 : t);   // clamp both ends
            const size_t gi = (size_t)(b * SS + tc) * HH + k;
            rows2[k][r]     = x[gi];
            rows2[k][6 + r] = ref[gi];
        }
        rows2[k][5]  = 0.f;
        rows2[k][11] = 0.f;
    }
    __syncthreads();

    // ---- accumulators ----
    float A[5][4], C[5][4], P[4][4];
    {
        const float4 ab = (q == 0) ? ((const float4*)b1)[hq]  : make_float4(0.f, 0.f, 0.f, 0.f);
        const float4 pb = (q == 0) ? ((const float4*)bp1)[hq] : make_float4(0.f, 0.f, 0.f, 0.f);
        #pragma unroll
        for (int r = 0; r < 5; r++) {
            A[r][0] = ab.x; A[r][1] = ab.y; A[r][2] = ab.z; A[r][3] = ab.w;
            C[r][0] = 0.f;  C[r][1] = 0.f;  C[r][2] = 0.f;  C[r][3] = 0.f;
        }
        #pragma unroll
        for (int r = 0; r < 4; r++) {
            P[r][0] = pb.x; P[r][1] = pb.y; P[r][2] = pb.z; P[r][3] = pb.w;
        }
    }

    const float4* __restrict__ Wa4 = (const float4*)Wa;   // [k*32 + hq]
    const float4* __restrict__ Wb4 = (const float4*)Wb;
    const float4* __restrict__ Wp4 = (const float4*)Wp1;

    const int kb = q * 32;

    // ---- prologue: load weights for first iteration ----
    float4 wa_c = Wa4[kb * 32 + hq];
    float4 wb_c = Wb4[kb * 32 + hq];
    float4 wp_c = Wp4[kb * 32 + hq];

    #pragma unroll 2
    for (int kk = 0; kk < 31; kk++) {
        const int k = kb + kk;
        // prefetch next iteration's weights (GMEM) before this iter's FMAs
        float4 wa_n = Wa4[(k + 1) * 32 + hq];
        float4 wb_n = Wb4[(k + 1) * 32 + hq];
        float4 wp_n = Wp4[(k + 1) * 32 + hq];

        const float4 u0 = *(const float4*)&rows2[k][0];   // x0 x1 x2 x3
        const float4 u1 = *(const float4*)&rows2[k][4];   // x4 pad r0 r1
        const float4 u2 = *(const float4*)&rows2[k][8];   // r2 r3 r4 pad
        const float xv[5]  = {u0.x, u0.y, u0.z, u0.w, u1.x};
        const float rv[5]  = {u1.z, u1.w, u2.x, u2.y, u2.z};
        const float waj[4] = {wa_c.x, wa_c.y, wa_c.z, wa_c.w};
        const float wbj[4] = {wb_c.x, wb_c.y, wb_c.z, wb_c.w};
        const float wpj[4] = {wp_c.x, wp_c.y, wp_c.z, wp_c.w};
        #pragma unroll
        for (int r = 0; r < 5; r++) {
            #pragma unroll
            for (int j = 0; j < 4; j++) {
                A[r][j] = fmaf(xv[r], waj[j], A[r][j]);
                C[r][j] = fmaf(rv[r], wbj[j], C[r][j]);
            }
        }
        #pragma unroll
        for (int r = 0; r < 4; r++) {
            #pragma unroll
            for (int j = 0; j < 4; j++)
                P[r][j] = fmaf(xv[r + 1], wpj[j], P[r][j]);
        }

        wa_c = wa_n; wb_c = wb_n; wp_c = wp_n;
    }
    // ---- epilogue iteration (kk = 31), no prefetch ----
    {
        const int k = kb + 31;
        const float4 u0 = *(const float4*)&rows2[k][0];
        const float4 u1 = *(const float4*)&rows2[k][4];
        const float4 u2 = *(const float4*)&rows2[k][8];
        const float xv[5]  = {u0.x, u0.y, u0.z, u0.w, u1.x};
        const float rv[5]  = {u1.z, u1.w, u2.x, u2.y, u2.z};
        const float waj[4] = {wa_c.x, wa_c.y, wa_c.z, wa_c.w};
        const float wbj[4] = {wb_c.x, wb_c.y, wb_c.z, wb_c.w};
        const float wpj[4] = {wp_c.x, wp_c.y, wp_c.z, wp_c.w};
        #pragma unroll
        for (int r = 0; r < 5; r++) {
            #pragma unroll
            for (int j = 0; j < 4; j++) {
                A[r][j] = fmaf(xv[r], waj[j], A[r][j]);
                C[r][j] = fmaf(rv[r], wbj[j], C[r][j]);
            }
        }
        #pragma unroll
        for (int r = 0; r < 4; r++) {
            #pragma unroll
            for (int j = 0; j < 4; j++)
                P[r][j] = fmaf(xv[r + 1], wpj[j], P[r][j]);
        }
    }

    // ---- publish partials (q = 1..3) ----
    if (q != 0) {
        #pragma unroll
        for (int r = 0; r < 5; r++) {
            #pragma unroll
            for (int j = 0; j < 4; j++) {
                part[q - 1][r * 4 + j][hq]      = A[r][j];
                part[q - 1][20 + r * 4 + j][hq] = C[r][j];
            }
        }
        #pragma unroll
        for (int r = 0; r < 4; r++) {
            #pragma unroll
            for (int j = 0; j < 4; j++)
                part[q - 1][40 + r * 4 + j][hq] = P[r][j];
        }
    }
    __syncthreads();

    // ---- q == 0: one warp finishes the block ----
    if (q == 0) {
        #pragma unroll
        for (int r = 0; r < 5; r++) {
            #pragma unroll
            for (int j = 0; j < 4; j++) {
                const int d = r * 4 + j;
                A[r][j] += part[0][d][hq]      + part[1][d][hq]      + part[2][d][hq];
                C[r][j] += part[0][20 + d][hq] + part[1][20 + d][hq] + part[2][20 + d][hq];
            }
        }
        #pragma unroll
        for (int r = 0; r < 4; r++) {
            #pragma unroll
            for (int j = 0; j < 4; j++) {
                const int d = 40 + r * 4 + j;
                P[r][j] += part[0][d][hq] + part[1][d][hq] + part[2][d][hq];
                P[r][j]  = fmaxf(P[r][j], 0.f);
            }
        }

        const float4 w2v = ((const float4*)W2)[hq];
        const float  w2a[4] = {w2v.x, w2v.y, w2v.z, w2v.w};
        const float4* wpq = (const float4*)&Wp2[12 * hq];
        const float4 q0v = wpq[0], q1v = wpq[1], q2v = wpq[2];
        const float wq[12] = {q0v.x, q0v.y, q0v.z, q0v.w,
                              q1v.x, q1v.y, q1v.z, q1v.w,
                              q2v.x, q2v.y, q2v.z, q2v.w};
        const float b2s  = b2[0];
        const float bp20 = bp2[0], bp21 = bp2[1], bp22 = bp2[2];

        #pragma unroll
        for (int i = 0; i < 4; i++) {
            if (i >= cnt) break;           // 3-row blocks skip the 4th row
            const int t = t0 + i;
            float v[6] = {0.f, 0.f, 0.f, 0.f, 0.f, 0.f};
            #pragma unroll
            for (int j = 0; j < 4; j++) {
                v[0] += fmaxf(A[i + 1][j] + C[i + 1][j], 0.f) * w2a[j];  // A[t,t]
                v[1] += fmaxf(A[i][j]     + C[i + 1][j], 0.f) * w2a[j];  // A[t-1,t]
                v[2] += fmaxf(A[i + 1][j] + C[i][j],     0.f) * w2a[j];  // A[t,t-1]
                const float pj = P[i][j];
                v[3] += pj * wq[3 * j + 0];
                v[4] += pj * wq[3 * j + 1];
                v[5] += pj * wq[3 * j + 2];
            }
            #pragma unroll
            for (int j = 0; j < 6; j++) {
                float s = v[j];
                s += __shfl_xor_sync(0xffffffffu, s, 16);
                s += __shfl_xor_sync(0xffffffffu, s, 8);
                s += __shfl_xor_sync(0xffffffffu, s, 4);
                s += __shfl_xor_sync(0xffffffffu, s, 2);
                s += __shfl_xor_sync(0xffffffffu, s, 1);
                v[j] = s;   // all lanes hold the full sum
            }

            // decision, computed redundantly on all 32 lanes
            int   op    = -1;    // -1 => copy x (t == 0)
            float alpha = 0.f;
            const float Ad = 1.0f / (1.0f + expf(-(v[0] + b2s)));
            if (t != 0) {
                const float Ai   = 1.0f / (1.0f + expf(-(v[1] + b2s)));
                const float Adel = 1.0f / (1.0f + expf(-(v[2] + b2s)));
                const float l0 = v[3] + bp20;
                const float l1 = v[4] + bp21;
                const float l2 = v[5] + bp22;
                const float mx  = fmaxf(l0, fmaxf(l1, l2));
                const float lse = mx + logf(expf(l0 - mx) + expf(l1 - mx) + expf(l2 - mx));
                const float m   = Ad   * (l0 - lse);
                const float ins = Ai   * (l1 - lse);
                const float del = Adel * (l2 - lse);
                if (m >= ins && m >= del) op = 0;   // first-max tie-break == jnp.argmax
                else if (ins >= del)      op = 1;
                else                      op = 2;
                alpha = Ad;
            }

            float o[4];
            #pragma unroll
            for (int j = 0; j < 4; j++) {
                const int hcol = 4 * hq + j;
                const float cx = rows2[hcol][i + 1];  // x[t]
                const float cr = rows2[hcol][7 + i];  // ref[t]
                const float px = rows2[hcol][i];      // x[t-1]
                if (op < 0)       o[j] = cx;
                else if (op == 0) o[j] = (1.f - alpha) * cx + alpha * cr;
                else if (op == 1) o[j] = cr;
                else              o[j] = px;
            }
            *(float4*)&out[(size_t)(b * SS + t) * HH + 4 * hq] =
                make_float4(o[0], o[1], o[2], o[3]);
        }
    }
}

extern "C" void kernel_launch(void* const* d_in, const int* in_sizes, int n_in,
                              void* d_out, int out_size) {
    const float* x   = (const float*)d_in[0];
    const float* ref = (const float*)d_in[1];
    const float* Wa  = (const float*)d_in[2];
    const float* Wb  = (const float*)d_in[3];
    const float* b1  = (const float*)d_in[4];
    const float* W2  = (const float*)d_in[5];
    const float* b2  = (const float*)d_in[6];
    const float* Wp1 = (const float*)d_in[7];
    const float* bp1 = (const float*)d_in[8];
    const float* Wp2 = (const float*)d_in[9];
    const float* bp2 = (const float*)d_in[10];

    dim3 grid(BB * 148);      // 592 blocks: 148 per batch, 4 per SM, one wave
    dim3 block(128);          // 32 h-quads x 4 k-quarters
    align_kernel<<<grid, block>>>(x, ref, Wa, Wb, b1, W2, b2,
                                  Wp1, bp1, Wp2, bp2, (float*)d_out);
}

// round 15
// speedup vs baseline: 1.5724x; 1.0194x over previous
#include <cuda_runtime.h>

#define BB 4
#define SS 512
#define HH 128

// 592 blocks (148/batch = exactly 4 blocks/SM, one balanced wave) x 128 threads.
// Per batch: blocks 0..67 own 4 rows, 68..147 own 3 rows (same code, clamped).
// Thread (hq = tid&31, q = tid>>5) owns h-quad {4hq..4hq+3}, k-quarter q (32 k).
// 56 scalar accumulators; GMEM weight loads software-pipelined one iter ahead.
// ALL quarters publish partials; then warp w finishes output row w in parallel.
__global__ __launch_bounds__(128, 4) void align_kernel(
    const float* __restrict__ x, const float* __restrict__ ref,
    const float* __restrict__ Wa, const float* __restrict__ Wb,
    const float* __restrict__ b1, const float* __restrict__ W2,
    const float* __restrict__ b2, const float* __restrict__ Wp1,
    const float* __restrict__ bp1, const float* __restrict__ Wp2,
    const float* __restrict__ bp2, float* __restrict__ out)
{
    const int tid = threadIdx.x;
    const int q   = tid >> 5;        // k-quarter 0..3 (= warp id)
    const int hq  = tid & 31;        // h-quad (h = 4hq .. 4hq+3)

    const int b   = blockIdx.x / 148;         // batch
    const int ib  = blockIdx.x - b * 148;     // block-in-batch 0..147
    int t0, cnt;
    if (ib < 68) { t0 = ib * 4;               cnt = 4; }
    else         { t0 = 272 + (ib - 68) * 3;  cnt = 3; }

    __shared__ float rows2[HH][12];     // [k][x0..x4,pad, r0..r4,pad], 48B stride
    __shared__ float part[4][56][32];   // partials from all 4 quarters

    // ---- stage rows transposed: thread tid owns k = tid ----
    {
        const int k = tid;
        #pragma unroll
        for (int r = 0; r < 5; r++) {
            int t  = t0 - 1 + r;
            int tc = t < 0 ? 0 : (t > SS - 1 ? SS - 1 : t);   // clamp both ends
            const size_t gi = (size_t)(b * SS + tc) * HH + k;
            rows2[k][r]     = x[gi];
            rows2[k][6 + r] = ref[gi];
        }
        rows2[k][5]  = 0.f;
        rows2[k][11] = 0.f;
    }
    __syncthreads();

    // ---- accumulators (bias added once, by quarter 0) ----
    float A[5][4], C[5][4], P[4][4];
    {
        const float4 ab = (q == 0) ? ((const float4*)b1)[hq]  : make_float4(0.f, 0.f, 0.f, 0.f);
        const float4 pb = (q == 0) ? ((const float4*)bp1)[hq] : make_float4(0.f, 0.f, 0.f, 0.f);
        #pragma unroll
        for (int r = 0; r < 5; r++) {
            A[r][0] = ab.x; A[r][1] = ab.y; A[r][2] = ab.z; A[r][3] = ab.w;
            C[r][0] = 0.f;  C[r][1] = 0.f;  C[r][2] = 0.f;  C[r][3] = 0.f;
        }
        #pragma unroll
        for (int r = 0; r < 4; r++) {
            P[r][0] = pb.x; P[r][1] = pb.y; P[r][2] = pb.z; P[r][3] = pb.w;
        }
    }

    const float4* __restrict__ Wa4 = (const float4*)Wa;   // [k*32 + hq]
    const float4* __restrict__ Wb4 = (const float4*)Wb;
    const float4* __restrict__ Wp4 = (const float4*)Wp1;

    const int kb = q * 32;

    // ---- prologue: load weights for first iteration ----
    float4 wa_c = Wa4[kb * 32 + hq];
    float4 wb_c = Wb4[kb * 32 + hq];
    float4 wp_c = Wp4[kb * 32 + hq];

    #pragma unroll 2
    for (int kk = 0; kk < 31; kk++) {
        const int k = kb + kk;
        // prefetch next iteration's weights (GMEM) before this iter's FMAs
        float4 wa_n = Wa4[(k + 1) * 32 + hq];
        float4 wb_n = Wb4[(k + 1) * 32 + hq];
        float4 wp_n = Wp4[(k + 1) * 32 + hq];

        const float4 u0 = *(const float4*)&rows2[k][0];   // x0 x1 x2 x3
        const float4 u1 = *(const float4*)&rows2[k][4];   // x4 pad r0 r1
        const float4 u2 = *(const float4*)&rows2[k][8];   // r2 r3 r4 pad
        const float xv[5]  = {u0.x, u0.y, u0.z, u0.w, u1.x};
        const float rv[5]  = {u1.z, u1.w, u2.x, u2.y, u2.z};
        const float waj[4] = {wa_c.x, wa_c.y, wa_c.z, wa_c.w};
        const float wbj[4] = {wb_c.x, wb_c.y, wb_c.z, wb_c.w};
        const float wpj[4] = {wp_c.x, wp_c.y, wp_c.z, wp_c.w};
        #pragma unroll
        for (int r = 0; r < 5; r++) {
            #pragma unroll
            for (int j = 0; j < 4; j++) {
                A[r][j] = fmaf(xv[r], waj[j], A[r][j]);
                C[r][j] = fmaf(rv[r], wbj[j], C[r][j]);
            }
        }
        #pragma unroll
        for (int r = 0; r < 4; r++) {
            #pragma unroll
            for (int j = 0; j < 4; j++)
                P[r][j] = fmaf(xv[r + 1], wpj[j], P[r][j]);
        }

        wa_c = wa_n; wb_c = wb_n; wp_c = wp_n;
    }
    // ---- epilogue iteration (kk = 31), no prefetch ----
    {
        const int k = kb + 31;
        const float4 u0 = *(const float4*)&rows2[k][0];
        const float4 u1 = *(const float4*)&rows2[k][4];
        const float4 u2 = *(const float4*)&rows2[k][8];
        const float xv[5]  = {u0.x, u0.y, u0.z, u0.w, u1.x};
        const float rv[5]  = {u1.z, u1.w, u2.x, u2.y, u2.z};
        const float waj[4] = {wa_c.x, wa_c.y, wa_c.z, wa_c.w};
        const float wbj[4] = {wb_c.x, wb_c.y, wb_c.z, wb_c.w};
        const float wpj[4] = {wp_c.x, wp_c.y, wp_c.z, wp_c.w};
        #pragma unroll
        for (int r = 0; r < 5; r++) {
            #pragma unroll
            for (int j = 0; j < 4; j++) {
                A[r][j] = fmaf(xv[r], waj[j], A[r][j]);
                C[r][j] = fmaf(rv[r], wbj[j], C[r][j]);
            }
        }
        #pragma unroll
        for (int r = 0; r < 4; r++) {
            #pragma unroll
            for (int j = 0; j < 4; j++)
                P[r][j] = fmaf(xv[r + 1], wpj[j], P[r][j]);
        }
    }

    // ---- ALL quarters publish partials ----
    #pragma unroll
    for (int r = 0; r < 5; r++) {
        #pragma unroll
        for (int j = 0; j < 4; j++) {
            part[q][r * 4 + j][hq]      = A[r][j];
            part[q][20 + r * 4 + j][hq] = C[r][j];
        }
    }
    #pragma unroll
    for (int r = 0; r < 4; r++) {
        #pragma unroll
        for (int j = 0; j < 4; j++)
            part[q][40 + r * 4 + j][hq] = P[r][j];
    }
    __syncthreads();

    // ---- parallel tail: warp w finishes output row i = w ----
    const int i = q;
    if (i < cnt) {
        const int t = t0 + i;

        // combine the 4 quarters for rows i (t-1) and i+1 (t), and P[i]
        float a0[4], a1[4], c0[4], c1[4], pw[4];
        #pragma unroll
        for (int j = 0; j < 4; j++) {
            const int dA0 = i * 4 + j;
            const int dA1 = (i + 1) * 4 + j;
            a0[j] = part[0][dA0][hq] + part[1][dA0][hq] + part[2][dA0][hq] + part[3][dA0][hq];
            a1[j] = part[0][dA1][hq] + part[1][dA1][hq] + part[2][dA1][hq] + part[3][dA1][hq];
            c0[j] = part[0][20 + dA0][hq] + part[1][20 + dA0][hq] + part[2][20 + dA0][hq] + part[3][20 + dA0][hq];
            c1[j] = part[0][20 + dA1][hq] + part[1][20 + dA1][hq] + part[2][20 + dA1][hq] + part[3][20 + dA1][hq];
            const int dP = 40 + i * 4 + j;
            pw[j] = fmaxf(part[0][dP][hq] + part[1][dP][hq] + part[2][dP][hq] + part[3][dP][hq], 0.f);
        }

        const float4 w2v = ((const float4*)W2)[hq];
        const float  w2a[4] = {w2v.x, w2v.y, w2v.z, w2v.w};
        const float4* wpq = (const float4*)&Wp2[12 * hq];
        const float4 q0v = wpq[0], q1v = wpq[1], q2v = wpq[2];
        const float wq[12] = {q0v.x, q0v.y, q0v.z, q0v.w,
                              q1v.x, q1v.y, q1v.z, q1v.w,
                              q2v.x, q2v.y, q2v.z, q2v.w};

        float v[6] = {0.f, 0.f, 0.f, 0.f, 0.f, 0.f};
        #pragma unroll
        for (int j = 0; j < 4; j++) {
            v[0] += fmaxf(a1[j] + c1[j], 0.f) * w2a[j];  // A[t,t]
            v[1] += fmaxf(a0[j] + c1[j], 0.f) * w2a[j];  // A[t-1,t]  (insert)
            v[2] += fmaxf(a1[j] + c0[j], 0.f) * w2a[j];  // A[t,t-1]  (delete)
            v[3] += pw[j] * wq[3 * j + 0];
            v[4] += pw[j] * wq[3 * j + 1];
            v[5] += pw[j] * wq[3 * j + 2];
        }
        #pragma unroll
        for (int j = 0; j < 6; j++) {
            float s = v[j];
            s += __shfl_xor_sync(0xffffffffu, s, 16);
            s += __shfl_xor_sync(0xffffffffu, s, 8);
            s += __shfl_xor_sync(0xffffffffu, s, 4);
            s += __shfl_xor_sync(0xffffffffu, s, 2);
            s += __shfl_xor_sync(0xffffffffu, s, 1);
            v[j] = s;   // all lanes hold the full sum
        }

        // decision, computed redundantly on all 32 lanes
        int   op    = -1;    // -1 => copy x (t == 0)
        float alpha = 0.f;
        const float b2s = b2[0];
        const float Ad  = 1.0f / (1.0f + expf(-(v[0] + b2s)));
        if (t != 0) {
            const float Ai   = 1.0f / (1.0f + expf(-(v[1] + b2s)));
            const float Adel = 1.0f / (1.0f + expf(-(v[2] + b2s)));
            const float l0 = v[3] + bp2[0];
            const float l1 = v[4] + bp2[1];
            const float l2 = v[5] + bp2[2];
            const float mx  = fmaxf(l0, fmaxf(l1, l2));
            const float lse = mx + logf(expf(l0 - mx) + expf(l1 - mx) + expf(l2 - mx));
            const float m   = Ad   * (l0 - lse);
            const float ins = Ai   * (l1 - lse);
            const float del = Adel * (l2 - lse);
            if (m >= ins && m >= del) op = 0;   // first-max tie-break == jnp.argmax
            else if (ins >= del)      op = 1;
            else                      op = 2;
            alpha = Ad;
        }

        // blend inputs via coalesced float4 LDG (L1-hot); no bank conflicts
        const int tm1 = (t > 0) ? (t - 1) : 0;
        const float4 cx4 = *(const float4*)&x[(size_t)(b * SS + t) * HH + 4 * hq];
        const float4 cr4 = *(const float4*)&ref[(size_t)(b * SS + t) * HH + 4 * hq];
        const float4 px4 = *(const float4*)&x[(size_t)(b * SS + tm1) * HH + 4 * hq];

        float4 o;
        if (op < 0) {
            o = cx4;
        } else if (op == 0) {
            o.x = (1.f - alpha) * cx4.x + alpha * cr4.x;
            o.y = (1.f - alpha) * cx4.y + alpha * cr4.y;
            o.z = (1.f - alpha) * cx4.z + alpha * cr4.z;
            o.w = (1.f - alpha) * cx4.w + alpha * cr4.w;
        } else if (op == 1) {
            o = cr4;
        } else {
            o = px4;
        }
        *(float4*)&out[(size_t)(b * SS + t) * HH + 4 * hq] = o;
    }
}

extern "C" void kernel_launch(void* const* d_in, const int* in_sizes, int n_in,
                              void* d_out, int out_size) {
    const float* x   = (const float*)d_in[0];
    const float* ref = (const float*)d_in[1];
    const float* Wa  = (const float*)d_in[2];
    const float* Wb  = (const float*)d_in[3];
    const float* b1  = (const float*)d_in[4];
    const float* W2  = (const float*)d_in[5];
    const float* b2  = (const float*)d_in[6];
    const float* Wp1 = (const float*)d_in[7];
    const float* bp1 = (const float*)d_in[8];
    const float* Wp2 = (const float*)d_in[9];
    const float* bp2 = (const float*)d_in[10];

    dim3 grid(BB * 148);      // 592 blocks: 148 per batch, 4 per SM, one wave
    dim3 block(128);          // 32 h-quads x 4 k-quarters
    align_kernel<<<grid, block>>>(x, ref, Wa, Wb, b1, W2, b2,
                                  Wp1, bp1, Wp2, bp2, (float*)d_out);
}